// round 7
// baseline (speedup 1.0000x reference)
#include <cuda_runtime.h>
#include <cuda_fp16.h>

#define B_SZ    512
#define FEATS   30
#define NNZ     (B_SZ * FEATS)
#define FT_OUT  512
#define N_FEAT  40960
#define N_VFEAT 640
#define GRID    128
#define ROUNDS  (FT_OUT / GRID)   // 4 k's per persistent CTA

// Packed indices, feature-major: g_packed[f*B + b] = stm_col | (nstm_col<<16)
__device__ unsigned g_packed[NNZ];
__device__ __half   g_vals[NNZ];
// Partial outputs, [k][b] layout -> coalesced writes and reads. 1 MB.
__device__ float    g_partial[FT_OUT * B_SZ];

// Dynamic smem: __half tbuf[2][N_FEAT]; __half fbuf[2][N_VFEAT];
#define SMEM_BYTES ((2 * N_FEAT + 2 * N_VFEAT) * 2)

static __device__ __forceinline__ unsigned h2u(__half2 h) {
    return *reinterpret_cast<unsigned*>(&h);
}

// ---------------------------------------------------------------------------
// Kernel 0: prepass. Pack cols into u32, values into fp16, feature-major
// (makes the main kernel's per-round index loads lane-coalesced).
// ---------------------------------------------------------------------------
__global__ void __launch_bounds__(256) pack_idx_kernel(
    const int*   __restrict__ stm_idx,    // [2, NNZ]; cols at offset NNZ
    const int*   __restrict__ nstm_idx,   // [2, NNZ]
    const float* __restrict__ values)     // [NNZ]
{
    const int e = blockIdx.x * 256 + threadIdx.x;
    if (e >= NNZ) return;
    const int b = e / FEATS;
    const int f = e % FEATS;
    const unsigned cs = (unsigned)stm_idx [NNZ + e];
    const unsigned cn = (unsigned)nstm_idx[NNZ + e];
    const int dst = f * B_SZ + b;
    g_packed[dst] = cs | (cn << 16);
    g_vals[dst]   = __float2half(values[e]);
}

// ---------------------------------------------------------------------------
// Kernel 1: persistent warp-specialized main kernel.
// 128 CTAs (1/SM), 512 threads: t<256 = streamers, t>=256 = computers.
// Each CTA handles k = c*4 .. c*4+3 with a double-buffered fused fp16 table
// (ft_w row + fft_w[c%640] pre-added). Round r: streamers fill buffer for
// k_{r+1} while computers consume the buffer for k_r. One __syncthreads per
// round. Computers apply bias+clip+out_w and write coalesced [k][b] partials.
// ---------------------------------------------------------------------------
__global__ void __launch_bounds__(512, 1) halfkp_main_kernel(
    const float* __restrict__ ft_w,      // [512, 40960]
    const float* __restrict__ fft_w,     // [512, 640]
    const float* __restrict__ ft_b,      // [512]
    const float* __restrict__ fft_b,     // [512]
    const float* __restrict__ out_w)     // [1, 1024]
{
    extern __shared__ __half sm[];
    __half* tb0 = sm;                       // table buffer 0 [N_FEAT]
    __half* tb1 = sm + N_FEAT;              // table buffer 1
    __half* fb0 = sm + 2 * N_FEAT;          // fft buffer 0 [N_VFEAT]
    __half* fb1 = fb0 + N_VFEAT;            // fft buffer 1

    const int c  = blockIdx.x;
    const int t  = threadIdx.x;
    const int k0 = c * ROUNDS;
    const bool is_stream = (t < 256);
    const int st = t;          // streamer lane
    const int ct = t - 256;    // computer lane

    __half* tbuf[2] = { tb0, tb1 };
    __half* fbuf[2] = { fb0, fb1 };

    // ---- streamer helpers ----
    auto fill_fft = [&](int k, __half* dst) {
        if (st < N_VFEAT / 4) {  // 160 threads, one float4 each
            float4 a = __ldg(reinterpret_cast<const float4*>(
                                 fft_w + (size_t)k * N_VFEAT) + st);
            uint2 p = make_uint2(h2u(__floats2half2_rn(a.x, a.y)),
                                 h2u(__floats2half2_rn(a.z, a.w)));
            reinterpret_cast<uint2*>(dst)[st] = p;
        }
    };
    auto stream_k = [&](int k, __half* dst, const __half* ff) {
        const float4* row = reinterpret_cast<const float4*>(
                                ft_w + (size_t)k * N_FEAT);
        #pragma unroll 4
        for (int i = 0; i < N_FEAT / 4 / 256; i++) {   // 40 iterations
            const int idx  = st + i * 256;
            const int ccol = idx * 4;
            const int m    = ccol % N_VFEAT;           // multiple of 4
            float4 a = __ldg(row + idx);
            __half2 f01 = *reinterpret_cast<const __half2*>(ff + m);
            __half2 f23 = *reinterpret_cast<const __half2*>(ff + m + 2);
            __half2 h01 = __hadd2(__floats2half2_rn(a.x, a.y), f01);
            __half2 h23 = __hadd2(__floats2half2_rn(a.z, a.w), f23);
            *reinterpret_cast<uint2*>(dst + ccol) = make_uint2(h2u(h01), h2u(h23));
        }
    };

    // ---- prologue: fft(k0); then table(k0) + fft(k0+1) ----
    if (is_stream) fill_fft(k0, fbuf[0]);
    __syncthreads();
    if (is_stream) { stream_k(k0, tbuf[0], fbuf[0]); fill_fft(k0 + 1, fbuf[1]); }
    __syncthreads();

    // ---- rounds ----
    for (int r = 0; r < ROUNDS; r++) {
        if (is_stream) {
            if (r + 1 < ROUNDS)
                stream_k(k0 + r + 1, tbuf[(r + 1) & 1], fbuf[(r + 1) & 1]);
            if (r + 2 < ROUNDS)
                fill_fft(k0 + r + 2, fbuf[r & 1]);   // safe: nobody reads it now
        } else {
            const __half* tb = tbuf[r & 1];
            const int k = k0 + r;
            float a0s = 0.f, a0n = 0.f, a1s = 0.f, a1n = 0.f;

            #pragma unroll
            for (int ch = 0; ch < 3; ch++) {          // chunks of 10 features
                unsigned p0[10], p1[10];
                __half   v0[10], v1[10];
                #pragma unroll
                for (int f = 0; f < 10; f++) {
                    const int fi = ch * 10 + f;
                    p0[f] = __ldg(g_packed + fi * B_SZ + ct);
                    p1[f] = __ldg(g_packed + fi * B_SZ + ct + 256);
                    v0[f] = g_vals[fi * B_SZ + ct];
                    v1[f] = g_vals[fi * B_SZ + ct + 256];
                }
                #pragma unroll
                for (int f = 0; f < 10; f++) {
                    const float vf0 = __half2float(v0[f]);
                    const float vf1 = __half2float(v1[f]);
                    a0s = fmaf(vf0, __half2float(tb[p0[f] & 0xFFFFu]), a0s);
                    a0n = fmaf(vf0, __half2float(tb[p0[f] >> 16]),     a0n);
                    a1s = fmaf(vf1, __half2float(tb[p1[f] & 0xFFFFu]), a1s);
                    a1n = fmaf(vf1, __half2float(tb[p1[f] >> 16]),     a1n);
                }
            }

            const float bias = __ldg(ft_b + k) + __ldg(fft_b + k);
            const float ws   = __ldg(out_w + k);
            const float wn   = __ldg(out_w + FT_OUT + k);

            g_partial[k * B_SZ + ct] =
                ws * __saturatef(a0s + bias) + wn * __saturatef(a0n + bias);
            g_partial[k * B_SZ + ct + 256] =
                ws * __saturatef(a1s + bias) + wn * __saturatef(a1n + bias);
        }
        __syncthreads();
    }
}

// ---------------------------------------------------------------------------
// Kernel 2: sum the 512 k-partials per batch row ([k][b] coalesced across b),
// add out_b, sigmoid. grid=16 x (32 b-lanes * 8 k-groups). Deterministic.
// ---------------------------------------------------------------------------
__global__ void __launch_bounds__(256) halfkp_reduce_kernel(
    const float* __restrict__ out_b,
    float*       __restrict__ out)       // [512]
{
    const int tx = threadIdx.x & 31;     // batch lane
    const int ty = threadIdx.x >> 5;     // k group (0..7), 64 k's each
    const int b  = blockIdx.x * 32 + tx;

    float s = 0.f;
    #pragma unroll 8
    for (int i = 0; i < FT_OUT / 8; i++)
        s += g_partial[(ty * (FT_OUT / 8) + i) * B_SZ + b];

    __shared__ float red[8][33];
    red[ty][tx] = s;
    __syncthreads();

    if (ty == 0) {
        float tot = __ldg(out_b);
        #pragma unroll
        for (int j = 0; j < 8; j++) tot += red[j][tx];
        out[b] = 1.0f / (1.0f + expf(-tot));
    }
}

// ---------------------------------------------------------------------------
extern "C" void kernel_launch(void* const* d_in, const int* in_sizes, int n_in,
                              void* d_out, int out_size) {
    const int*   stm_idx  = (const int*)  d_in[0];
    const int*   nstm_idx = (const int*)  d_in[1];
    const float* values   = (const float*)d_in[2];
    const float* ft_w     = (const float*)d_in[3];
    const float* ft_b     = (const float*)d_in[4];
    const float* fft_w    = (const float*)d_in[5];
    const float* fft_b    = (const float*)d_in[6];
    const float* out_w    = (const float*)d_in[7];
    const float* out_b    = (const float*)d_in[8];
    float*       out      = (float*)d_out;

    (void)in_sizes; (void)n_in; (void)out_size;

    cudaFuncSetAttribute(halfkp_main_kernel,
                         cudaFuncAttributeMaxDynamicSharedMemorySize, SMEM_BYTES);

    pack_idx_kernel<<<(NNZ + 255) / 256, 256>>>(stm_idx, nstm_idx, values);

    halfkp_main_kernel<<<GRID, 512, SMEM_BYTES>>>(
        ft_w, fft_w, ft_b, fft_b, out_w);

    halfkp_reduce_kernel<<<B_SZ / 32, 256>>>(out_b, out);
}

// round 8
// speedup vs baseline: 2.5514x; 2.5514x over previous
#include <cuda_runtime.h>
#include <cuda_fp16.h>

#define B_SZ    512
#define FEATS   30
#define NNZ     (B_SZ * FEATS)
#define FT_OUT  512
#define N_FEAT  40960
#define N_VFEAT 640

// Packed indices, feature-major: g_packed[f*B + b] = stm_col | (nstm_col<<16)
__device__ unsigned g_packed[NNZ];
__device__ __half   g_vals[NNZ];          // values, feature-major, fp16
// Partial outputs, [k][b] layout -> coalesced stores and reads. 1 MB.
__device__ float    g_partial[FT_OUT * B_SZ];

// Dynamic smem: __half sft[N_FEAT] (fused ft+fft table), __half sfft[N_VFEAT]
#define SMEM_BYTES ((N_FEAT + N_VFEAT) * 2)

static __device__ __forceinline__ unsigned h2u(__half2 h) {
    return *reinterpret_cast<unsigned*>(&h);
}

// ---------------------------------------------------------------------------
// Kernel 0: prepass. Pack cols into u32, values into fp16, feature-major so
// the main kernel's Phase C loads are lane-coalesced. Runs CONCURRENTLY with
// the main kernel's streaming phase via PDL.
// ---------------------------------------------------------------------------
__global__ void __launch_bounds__(256) pack_idx_kernel(
    const int*   __restrict__ stm_idx,    // [2, NNZ]; cols at offset NNZ
    const int*   __restrict__ nstm_idx,   // [2, NNZ]
    const float* __restrict__ values)     // [NNZ]
{
    const int e = blockIdx.x * 256 + threadIdx.x;
    if (e >= NNZ) return;
    const int b = e / FEATS;
    const int f = e % FEATS;
    const unsigned cs = (unsigned)stm_idx [NNZ + e];
    const unsigned cn = (unsigned)nstm_idx[NNZ + e];
    const int dst = f * B_SZ + b;
    g_packed[dst] = cs | (cn << 16);
    g_vals[dst]   = __float2half(values[e]);
}

// ---------------------------------------------------------------------------
// Kernel 1: one CTA per output unit k (512 CTAs, 512 threads, 2 CTAs/SM).
// Phase A: fft_w row k -> smem fp16.
// Phase B: stream ft_w row k, fusing sfft[c%640] -> sft[c] (fp16, 80 KB).
// (PDL grid sync: the pack prepass finishes under Phase A/B.)
// Phase C: thread t = batch row t. Coalesced feature-major packed-index
//          loads, 2 random LDS.16 per feature, bias+clip+out_w partial.
// Stores g_partial[k][t] fully coalesced.
// ---------------------------------------------------------------------------
__global__ void __launch_bounds__(512, 2) halfkp_k_kernel(
    const float* __restrict__ ft_w,      // [512, 40960]
    const float* __restrict__ ft_b,      // [512]
    const float* __restrict__ fft_w,     // [512, 640]
    const float* __restrict__ fft_b,     // [512]
    const float* __restrict__ out_w)     // [1, 1024]
{
    extern __shared__ char smem_raw[];
    __half* sft  = reinterpret_cast<__half*>(smem_raw);            // [N_FEAT]
    __half* sfft = sft + N_FEAT;                                   // [N_VFEAT]

    const int k = blockIdx.x;
    const int t = threadIdx.x;

    // ---- Phase A ----
    if (t < N_VFEAT / 4) {   // 160 threads, one float4 each
        float4 a = __ldg(reinterpret_cast<const float4*>(
                             fft_w + (size_t)k * N_VFEAT) + t);
        uint2 p = make_uint2(h2u(__floats2half2_rn(a.x, a.y)),
                             h2u(__floats2half2_rn(a.z, a.w)));
        reinterpret_cast<uint2*>(sfft)[t] = p;
    }
    __syncthreads();

    // ---- Phase B: stream + fuse ----
    {
        const float4* row = reinterpret_cast<const float4*>(
                                ft_w + (size_t)k * N_FEAT);
        #pragma unroll
        for (int i = 0; i < N_FEAT / 4 / 512; i++) {   // 20 iterations
            const int idx = t + i * 512;
            const int c   = idx * 4;
            const int m   = c % N_VFEAT;               // multiple of 4
            float4 a = __ldg(row + idx);
            __half2 f01 = *reinterpret_cast<const __half2*>(sfft + m);
            __half2 f23 = *reinterpret_cast<const __half2*>(sfft + m + 2);
            __half2 h01 = __hadd2(__floats2half2_rn(a.x, a.y), f01);
            __half2 h23 = __hadd2(__floats2half2_rn(a.z, a.w), f23);
            uint2 p = make_uint2(h2u(h01), h2u(h23));
            *reinterpret_cast<uint2*>(sft + c) = p;
        }
    }
    __syncthreads();

    // PDL: pack prepass must be complete (and visible) before Phase C.
    cudaGridDependencySynchronize();

    // ---- Phase C: thread t = batch row t; coalesced index loads ----
    float accs = 0.f, accn = 0.f;

    #pragma unroll
    for (int c = 0; c < 3; c++) {                      // chunks of 10 features
        unsigned p[10];
        __half   v[10];
        #pragma unroll
        for (int f = 0; f < 10; f++) {
            const int idx = (c * 10 + f) * B_SZ + t;   // lane-consecutive
            p[f] = __ldg(g_packed + idx);
            v[f] = g_vals[idx];
        }
        #pragma unroll
        for (int f = 0; f < 10; f++) {
            const float vf = __half2float(v[f]);
            accs = fmaf(vf, __half2float(sft[p[f] & 0xFFFFu]), accs);
            accn = fmaf(vf, __half2float(sft[p[f] >> 16]),     accn);
        }
    }

    const float bias = __ldg(ft_b + k) + __ldg(fft_b + k);
    const float hs = __saturatef(accs + bias);
    const float hn = __saturatef(accn + bias);
    const float part = hs * __ldg(out_w + k) + hn * __ldg(out_w + FT_OUT + k);

    g_partial[k * B_SZ + t] = part;                    // coalesced [k][b]
}

// ---------------------------------------------------------------------------
// Kernel 2: sum the 512 k-partials per batch row ([k][b], coalesced along b),
// add out_b, sigmoid. grid=16 x (32 b-lanes * 8 k-groups). Deterministic
// fixed-order summation. PDL: overlaps prologue with main kernel tail.
// ---------------------------------------------------------------------------
__global__ void __launch_bounds__(256) halfkp_reduce_kernel(
    const float* __restrict__ out_b,
    float*       __restrict__ out)       // [512]
{
    const int tx = threadIdx.x & 31;     // batch lane
    const int ty = threadIdx.x >> 5;     // k group (0..7), 64 k's each
    const int b  = blockIdx.x * 32 + tx;

    cudaGridDependencySynchronize();     // wait for main kernel's g_partial

    float s = 0.f;
    #pragma unroll 8
    for (int i = 0; i < FT_OUT / 8; i++)
        s += g_partial[(ty * (FT_OUT / 8) + i) * B_SZ + b];

    __shared__ float red[8][33];
    red[ty][tx] = s;
    __syncthreads();

    if (ty == 0) {
        float tot = __ldg(out_b);
        #pragma unroll
        for (int j = 0; j < 8; j++) tot += red[j][tx];
        out[b] = 1.0f / (1.0f + expf(-tot));
    }
}

// ---------------------------------------------------------------------------
extern "C" void kernel_launch(void* const* d_in, const int* in_sizes, int n_in,
                              void* d_out, int out_size) {
    const int*   stm_idx  = (const int*)  d_in[0];
    const int*   nstm_idx = (const int*)  d_in[1];
    const float* values   = (const float*)d_in[2];
    const float* ft_w     = (const float*)d_in[3];
    const float* ft_b     = (const float*)d_in[4];
    const float* fft_w    = (const float*)d_in[5];
    const float* fft_b    = (const float*)d_in[6];
    const float* out_w    = (const float*)d_in[7];
    const float* out_b    = (const float*)d_in[8];
    float*       out      = (float*)d_out;

    (void)in_sizes; (void)n_in; (void)out_size;

    cudaFuncSetAttribute(halfkp_k_kernel,
                         cudaFuncAttributeMaxDynamicSharedMemorySize, SMEM_BYTES);

    pack_idx_kernel<<<(NNZ + 255) / 256, 256>>>(stm_idx, nstm_idx, values);

    // Main kernel with Programmatic Dependent Launch: starts while the pack
    // kernel is still running; grid-syncs before Phase C reads packed data.
    {
        cudaLaunchConfig_t cfg = {};
        cfg.gridDim          = dim3(FT_OUT);
        cfg.blockDim         = dim3(512);
        cfg.dynamicSmemBytes = SMEM_BYTES;
        cfg.stream           = 0;
        cudaLaunchAttribute at[1];
        at[0].id = cudaLaunchAttributeProgrammaticStreamSerialization;
        at[0].val.programmaticStreamSerializationAllowed = 1;
        cfg.attrs    = at;
        cfg.numAttrs = 1;
        cudaLaunchKernelEx(&cfg, halfkp_k_kernel,
                           ft_w, ft_b, fft_w, fft_b, out_w);
    }

    // Reduce with PDL: prologue overlaps the main kernel's tail.
    {
        cudaLaunchConfig_t cfg = {};
        cfg.gridDim  = dim3(B_SZ / 32);
        cfg.blockDim = dim3(256);
        cfg.stream   = 0;
        cudaLaunchAttribute at[1];
        at[0].id = cudaLaunchAttributeProgrammaticStreamSerialization;
        at[0].val.programmaticStreamSerializationAllowed = 1;
        cfg.attrs    = at;
        cfg.numAttrs = 1;
        cudaLaunchKernelEx(&cfg, halfkp_reduce_kernel, out_b, out);
    }
}

// round 9
// speedup vs baseline: 2.7599x; 1.0817x over previous
#include <cuda_runtime.h>
#include <cuda_fp16.h>

#define B_SZ    512
#define FEATS   30
#define NNZ     (B_SZ * FEATS)
#define FT_OUT  512
#define N_FEAT  40960
#define N_VFEAT 640

// Packed indices, feature-major: g_packed[f*B + b] = stm_col | (nstm_col<<16)
__device__ unsigned g_packed[NNZ];
__device__ __half   g_vals[NNZ];          // values, feature-major, fp16
// Partial outputs, [k][b] layout -> coalesced stores and reads. 1 MB.
__device__ float    g_partial[FT_OUT * B_SZ];

// Dynamic smem: __half sft[N_FEAT] (fused ft+fft table), __half sfft[N_VFEAT]
#define SMEM_BYTES ((N_FEAT + N_VFEAT) * 2)

static __device__ __forceinline__ unsigned h2u(__half2 h) {
    return *reinterpret_cast<unsigned*>(&h);
}

// ---------------------------------------------------------------------------
// Kernel 0: prepass. Pack cols into u32, values into fp16, feature-major so
// the main kernel's Phase C loads are lane-coalesced. Triggers programmatic
// launch completion IMMEDIATELY so the main kernel starts streaming ft_w
// while this kernel is still running.
// ---------------------------------------------------------------------------
__global__ void __launch_bounds__(256) pack_idx_kernel(
    const int*   __restrict__ stm_idx,    // [2, NNZ]; cols at offset NNZ
    const int*   __restrict__ nstm_idx,   // [2, NNZ]
    const float* __restrict__ values)     // [NNZ]
{
    cudaTriggerProgrammaticLaunchCompletion();   // let main kernel launch NOW

    const int e = blockIdx.x * 256 + threadIdx.x;
    if (e >= NNZ) return;
    const int b = e / FEATS;
    const int f = e % FEATS;
    const unsigned cs = (unsigned)stm_idx [NNZ + e];
    const unsigned cn = (unsigned)nstm_idx[NNZ + e];
    const int dst = f * B_SZ + b;
    g_packed[dst] = cs | (cn << 16);
    g_vals[dst]   = __float2half(values[e]);
}

// ---------------------------------------------------------------------------
// Kernel 1: one CTA per output unit k (512 CTAs, 512 threads, 2 CTAs/SM).
// Phase A: fft_w row k -> smem fp16.
// Phase B: stream ft_w row k, fusing fft[c%640] -> sft[c] (fp16, 80 KB).
//          The fft offset pattern has period 5 -> 5 register-cached pairs.
// (PDL grid sync: the pack prepass finishes under Phase A/B.)
// Phase C: thread t = batch row t. Coalesced feature-major packed-index
//          loads, 2 random LDS.16 per feature, bias+clip+out_w partial.
// ---------------------------------------------------------------------------
__global__ void __launch_bounds__(512, 2) halfkp_k_kernel(
    const float* __restrict__ ft_w,      // [512, 40960]
    const float* __restrict__ ft_b,      // [512]
    const float* __restrict__ fft_w,     // [512, 640]
    const float* __restrict__ fft_b,     // [512]
    const float* __restrict__ out_w)     // [1, 1024]
{
    cudaTriggerProgrammaticLaunchCompletion();   // let reduce kernel launch

    extern __shared__ char smem_raw[];
    __half* sft  = reinterpret_cast<__half*>(smem_raw);            // [N_FEAT]
    __half* sfft = sft + N_FEAT;                                   // [N_VFEAT]

    const int k = blockIdx.x;
    const int t = threadIdx.x;

    // ---- Phase A: fft_w row k -> smem fp16 ----
    if (t < N_VFEAT / 4) {   // 160 threads, one float4 each
        float4 a = __ldg(reinterpret_cast<const float4*>(
                             fft_w + (size_t)k * N_VFEAT) + t);
        uint2 p = make_uint2(h2u(__floats2half2_rn(a.x, a.y)),
                             h2u(__floats2half2_rn(a.z, a.w)));
        reinterpret_cast<uint2*>(sfft)[t] = p;
    }
    __syncthreads();

    // ---- Phase B: stream + fuse. m_i = (4t + 128*i) % 640, period 5. ----
    {
        // Preload the 5 distinct fft pairs this thread will ever need.
        __half2 fA[5], fB[5];
        #pragma unroll
        for (int j = 0; j < 5; j++) {
            const int m = (4 * t + 128 * j) % N_VFEAT;
            fA[j] = *reinterpret_cast<const __half2*>(sfft + m);
            fB[j] = *reinterpret_cast<const __half2*>(sfft + m + 2);
        }

        const float4* row = reinterpret_cast<const float4*>(
                                ft_w + (size_t)k * N_FEAT);
        #pragma unroll
        for (int i = 0; i < N_FEAT / 4 / 512; i++) {   // 20 iterations
            const int idx = t + i * 512;
            const int c   = idx * 4;
            const int j   = i % 5;                     // static per unrolled iter
            float4 a = __ldg(row + idx);
            __half2 h01 = __hadd2(__floats2half2_rn(a.x, a.y), fA[j]);
            __half2 h23 = __hadd2(__floats2half2_rn(a.z, a.w), fB[j]);
            *reinterpret_cast<uint2*>(sft + c) = make_uint2(h2u(h01), h2u(h23));
        }
    }
    __syncthreads();

    // PDL: pack prepass must be complete (and visible) before Phase C.
    cudaGridDependencySynchronize();

    // ---- Phase C: thread t = batch row t; coalesced index loads ----
    float accs = 0.f, accn = 0.f;

    #pragma unroll
    for (int c = 0; c < 3; c++) {                      // chunks of 10 features
        unsigned p[10];
        __half   v[10];
        #pragma unroll
        for (int f = 0; f < 10; f++) {
            const int idx = (c * 10 + f) * B_SZ + t;   // lane-consecutive
            p[f] = __ldg(g_packed + idx);
            v[f] = g_vals[idx];
        }
        #pragma unroll
        for (int f = 0; f < 10; f++) {
            const float vf = __half2float(v[f]);
            accs = fmaf(vf, __half2float(sft[p[f] & 0xFFFFu]), accs);
            accn = fmaf(vf, __half2float(sft[p[f] >> 16]),     accn);
        }
    }

    const float bias = __ldg(ft_b + k) + __ldg(fft_b + k);
    const float hs = __saturatef(accs + bias);
    const float hn = __saturatef(accn + bias);
    const float part = hs * __ldg(out_w + k) + hn * __ldg(out_w + FT_OUT + k);

    g_partial[k * B_SZ + t] = part;                    // coalesced [k][b]
}

// ---------------------------------------------------------------------------
// Kernel 2: sum the 512 k-partials per batch row ([k][b], coalesced along b),
// add out_b, sigmoid. grid=16 x (32 b-lanes * 8 k-groups). Deterministic
// fixed-order summation. Launches early via PDL; parks in grid-sync.
// ---------------------------------------------------------------------------
__global__ void __launch_bounds__(256) halfkp_reduce_kernel(
    const float* __restrict__ out_b,
    float*       __restrict__ out)       // [512]
{
    const int tx = threadIdx.x & 31;     // batch lane
    const int ty = threadIdx.x >> 5;     // k group (0..7), 64 k's each
    const int b  = blockIdx.x * 32 + tx;

    cudaGridDependencySynchronize();     // wait for main kernel's g_partial

    float s = 0.f;
    #pragma unroll 8
    for (int i = 0; i < FT_OUT / 8; i++)
        s += g_partial[(ty * (FT_OUT / 8) + i) * B_SZ + b];

    __shared__ float red[8][33];
    red[ty][tx] = s;
    __syncthreads();

    if (ty == 0) {
        float tot = __ldg(out_b);
        #pragma unroll
        for (int j = 0; j < 8; j++) tot += red[j][tx];
        out[b] = 1.0f / (1.0f + expf(-tot));
    }
}

// ---------------------------------------------------------------------------
extern "C" void kernel_launch(void* const* d_in, const int* in_sizes, int n_in,
                              void* d_out, int out_size) {
    const int*   stm_idx  = (const int*)  d_in[0];
    const int*   nstm_idx = (const int*)  d_in[1];
    const float* values   = (const float*)d_in[2];
    const float* ft_w     = (const float*)d_in[3];
    const float* ft_b     = (const float*)d_in[4];
    const float* fft_w    = (const float*)d_in[5];
    const float* fft_b    = (const float*)d_in[6];
    const float* out_w    = (const float*)d_in[7];
    const float* out_b    = (const float*)d_in[8];
    float*       out      = (float*)d_out;

    (void)in_sizes; (void)n_in; (void)out_size;

    cudaFuncSetAttribute(halfkp_k_kernel,
                         cudaFuncAttributeMaxDynamicSharedMemorySize, SMEM_BYTES);

    pack_idx_kernel<<<(NNZ + 255) / 256, 256>>>(stm_idx, nstm_idx, values);

    // Main kernel with PDL: starts while the pack kernel is still running
    // (pack triggers at its first instruction); grid-syncs before Phase C.
    {
        cudaLaunchConfig_t cfg = {};
        cfg.gridDim          = dim3(FT_OUT);
        cfg.blockDim         = dim3(512);
        cfg.dynamicSmemBytes = SMEM_BYTES;
        cfg.stream           = 0;
        cudaLaunchAttribute at[1];
        at[0].id = cudaLaunchAttributeProgrammaticStreamSerialization;
        at[0].val.programmaticStreamSerializationAllowed = 1;
        cfg.attrs    = at;
        cfg.numAttrs = 1;
        cudaLaunchKernelEx(&cfg, halfkp_k_kernel,
                           ft_w, ft_b, fft_w, fft_b, out_w);
    }

    // Reduce with PDL: launches early, parks in grid-sync.
    {
        cudaLaunchConfig_t cfg = {};
        cfg.gridDim  = dim3(B_SZ / 32);
        cfg.blockDim = dim3(256);
        cfg.stream   = 0;
        cudaLaunchAttribute at[1];
        at[0].id = cudaLaunchAttributeProgrammaticStreamSerialization;
        at[0].val.programmaticStreamSerializationAllowed = 1;
        cfg.attrs    = at;
        cfg.numAttrs = 1;
        cudaLaunchKernelEx(&cfg, halfkp_reduce_kernel, out_b, out);
    }
}